// round 12
// baseline (speedup 1.0000x reference)
#include <cuda_runtime.h>

#define HH 224
#define WW 224
#define CH 32
#define TM 4
#define NB 8

// Block (32,16) = 512 threads, one 32x32 output tile per (t,c).
// Each thread: 2 j-pixels. Phases of 2 batch-planes, 4-buffer smem rotation,
// one __syncthreads per phase. Software pipeline: phase ph+1's 16 LDGs are
// issued before phase ph's barrier, so gather latency overlaps the whole
// store phase + barrier instead of stalling the STS.
__global__ __launch_bounds__(512)
void persp_kernel(const float* __restrict__ in,
                  const float* __restrict__ wt,
                  float* __restrict__ out)
{
    __shared__ float tile[4][32][33];   // [buf][j_local][i_local], pad 33

    const int tx  = threadIdx.x;        // i_local (gather-contiguous axis)
    const int ty  = threadIdx.y;        // j_local base (handles ty and ty+16)
    const int tid = ty * 32 + tx;
    const int j0 = blockIdx.x * 32;
    const int i0 = blockIdx.y * 32;
    const int oc = blockIdx.z;          // oc = c*TM + t
    const int c  = oc >> 2;
    const int t  = oc & 3;

    const float* m = wt + ((t * CH) + c) * 8;
    const float m0 = m[0], m1 = m[1], m2 = m[2];
    const float m3 = m[3], m4 = m[4], m5 = m[5];
    const float m6 = m[6], m7 = m[7];

    const float step = 2.0f / 223.0f;
    const int i = i0 + tx;
    const float xl = fmaf((float)i, step, -1.0f);   // linspace along H (i)

    int   o0[2], o1[2], o2[2], o3[2];
    float wa[2], wb[2], wc[2], wd[2];

    #pragma unroll
    for (int h = 0; h < 2; h++) {
        const int j = j0 + ty + 16 * h;
        const float yl = fmaf((float)j, step, -1.0f);

        const float X = fmaf(m0, xl, fmaf(m1, yl, m2));
        const float Y = fmaf(m3, xl, fmaf(m4, yl, m5));
        const float O = fmaf(m6, xl, fmaf(m7, yl, 1.0f));
        const float r = 1.0f / O;                   // accurate recip
        const float xs = X * r;
        const float ys = Y * r;

        const float x = 0.5f * ((xs + 1.0f) * 222.0f);
        const float y = 0.5f * ((ys + 1.0f) * 222.0f);

        int x0 = (int)floorf(x), x1 = x0 + 1;
        int y0 = (int)floorf(y), y1 = y0 + 1;
        x0 = min(max(x0, 0), WW - 1);
        x1 = min(max(x1, 0), WW - 1);
        y0 = min(max(y0, 0), HH - 1);
        y1 = min(max(y1, 0), HH - 1);
        const float x0f = (float)x0, x1f = (float)x1;
        const float y0f = (float)y0, y1f = (float)y1;

        // Reference's exact (quirky) weights: wb uses (y1f - y0f).
        wa[h] = (x1f - x) * (y1f - y);
        wb[h] = (x1f - x) * (y1f - y0f);
        wc[h] = (x - x0f) * (y1f - y);
        wd[h] = (x - x0f) * (y - y0f);

        const int ba  = y0 * WW + x0;
        const int dx  = x1 - x0;
        const int dyW = (y1 - y0) * WW;
        o0[h] = ba;
        o1[h] = ba + dx;
        o2[h] = ba + dyW;
        o3[h] = ba + dyW + dx;
    }

    const int plane = HH * WW;
    const size_t nstride = (size_t)CH * plane;      // elements per batch image
    const float* inp = in + (size_t)c * plane;

    // Store-phase assignment: 512 threads -> 512 STG.128 per phase.
    const int n_sub = tid >> 8;          // which of the 2 planes in the phase
    const int rem   = tid & 255;
    const int i_loc = rem >> 3;          // 0..31
    const int jc    = rem & 7;           // float4 chunk along j
    float* oq = out + (size_t)oc * plane
                    + (size_t)(i0 + i_loc) * WW + (j0 + 4 * jc);

    // ---- Prologue: prefetch phase 0 (2 planes x 2 halves x 4 corners) ----
    float v[2][2][4];
    #pragma unroll
    for (int nn = 0; nn < 2; nn++) {
        const float* p = inp + (size_t)nn * nstride;
        #pragma unroll
        for (int h = 0; h < 2; h++) {
            v[nn][h][0] = __ldg(p + o0[h]);
            v[nn][h][1] = __ldg(p + o1[h]);
            v[nn][h][2] = __ldg(p + o2[h]);
            v[nn][h][3] = __ldg(p + o3[h]);
        }
    }

    #pragma unroll
    for (int ph = 0; ph < NB / 2; ph++) {
        const int pair = (ph & 1) * 2;

        // ---- Consume current phase's prefetched values into smem ----
        #pragma unroll
        for (int nn = 0; nn < 2; nn++) {
            #pragma unroll
            for (int h = 0; h < 2; h++) {
                tile[pair + nn][ty + 16 * h][tx] =
                    wa[h] * v[nn][h][0] + wb[h] * v[nn][h][2] +
                    wc[h] * v[nn][h][1] + wd[h] * v[nn][h][3];
            }
        }

        // ---- Prefetch next phase BEFORE the barrier: latency overlaps the
        //      entire store phase + barrier of this phase. ----
        float vn[2][2][4];
        if (ph < NB / 2 - 1) {
            #pragma unroll
            for (int nn = 0; nn < 2; nn++) {
                const float* p = inp + (size_t)(2 * ph + 2 + nn) * nstride;
                #pragma unroll
                for (int h = 0; h < 2; h++) {
                    vn[nn][h][0] = __ldg(p + o0[h]);
                    vn[nn][h][1] = __ldg(p + o1[h]);
                    vn[nn][h][2] = __ldg(p + o2[h]);
                    vn[nn][h][3] = __ldg(p + o3[h]);
                }
            }
        }

        // One barrier per phase: publishes this pair for the store phase; the
        // previous phase's barrier ordered the other pair's stores before the
        // STS above overwrote it (4-buffer rotation, period 2 phases).
        __syncthreads();

        // ---- Store: transposed LDS (conflict-free via pad-33), STG.128 ----
        const int n = 2 * ph + n_sub;
        float4 r4;
        r4.x = tile[pair + n_sub][4 * jc + 0][i_loc];
        r4.y = tile[pair + n_sub][4 * jc + 1][i_loc];
        r4.z = tile[pair + n_sub][4 * jc + 2][i_loc];
        r4.w = tile[pair + n_sub][4 * jc + 3][i_loc];
        *(float4*)(oq + (size_t)n * TM * nstride) = r4;

        // ---- Rotate registers (resolved by unroll, no moves in SASS) ----
        #pragma unroll
        for (int nn = 0; nn < 2; nn++)
            #pragma unroll
            for (int h = 0; h < 2; h++)
                #pragma unroll
                for (int q = 0; q < 4; q++)
                    v[nn][h][q] = vn[nn][h][q];
    }
}

extern "C" void kernel_launch(void* const* d_in, const int* in_sizes, int n_in,
                              void* d_out, int out_size)
{
    const float* in = (const float*)d_in[0];   // inputs  (8,32,224,224) f32
    const float* wt = (const float*)d_in[1];   // wt_pers (4,32,8)       f32
    float* out = (float*)d_out;                // (8,128,224,224) f32

    dim3 block(32, 16);
    dim3 grid(WW / 32, HH / 32, CH * TM);      // 7 x 7 x 128
    persp_kernel<<<grid, block>>>(in, wt, out);
}